// round 14
// baseline (speedup 1.0000x reference)
#include <cuda_runtime.h>
#include <cuda_fp16.h>
#include <cstdint>

#define DINLINE __device__ __forceinline__

// ---------------- problem constants ----------------
constexpr int M_TOK = 8192;
constexpr int N_OUT = 4096;
constexpr int K_IN  = 4096;

constexpr int BM = 128;
constexpr int BN = 128;
constexpr int BK = 64;                     // 64 fp16 = 128B row (swizzle atom)
constexpr int STAGES = 3;
constexpr int KCHUNKS = K_IN / BK;         // 64
constexpr int MT = M_TOK / BM;             // 64
constexpr int NT = N_OUT / BN;             // 32

constexpr int A_BYTES  = BM * BK * 2;      // 16384
constexpr int STAGE_B  = 2 * A_BYTES;      // 32768 (A + W)
constexpr int SMEM_TOTAL = STAGES * STAGE_B;  // 98304 -> 2 CTAs/SM

// ---------------- scratch (allocation-free: __device__ globals) ----------------
__device__ __align__(16) __half g_Ah[(size_t)M_TOK * K_IN];   // 64 MB
__device__ __align__(16) __half g_Wh[(size_t)N_OUT * K_IN];   // 32 MB

// ---------------- PTX helpers (sm_80-era, legal on plain compute_103) --------
DINLINE uint32_t smem_u32(const void* p) {
    uint32_t a;
    asm volatile("{ .reg .u64 t; cvta.to.shared.u64 t, %1; cvt.u32.u64 %0, t; }"
                 : "=r"(a) : "l"(p));
    return a;
}
DINLINE void cp16(uint32_t dst, const void* src) {
    asm volatile("cp.async.cg.shared.global [%0], [%1], 16;"
                 :: "r"(dst), "l"(__cvta_generic_to_global(src)) : "memory");
}
DINLINE void cp_commit() { asm volatile("cp.async.commit_group;" ::: "memory"); }
template <int N> DINLINE void cp_wait() {
    asm volatile("cp.async.wait_group %0;" :: "n"(N) : "memory");
}
DINLINE void ldsm4(uint32_t& r0, uint32_t& r1, uint32_t& r2, uint32_t& r3, uint32_t a) {
    asm volatile("ldmatrix.sync.aligned.m8n8.x4.shared.b16 {%0,%1,%2,%3}, [%4];"
                 : "=r"(r0), "=r"(r1), "=r"(r2), "=r"(r3) : "r"(a));
}
DINLINE void mma16816(float* c, const uint32_t* a, uint32_t b0, uint32_t b1) {
    asm volatile(
        "mma.sync.aligned.m16n8k16.row.col.f32.f16.f16.f32 "
        "{%0,%1,%2,%3}, {%4,%5,%6,%7}, {%8,%9}, {%0,%1,%2,%3};"
        : "+f"(c[0]), "+f"(c[1]), "+f"(c[2]), "+f"(c[3])
        : "r"(a[0]), "r"(a[1]), "r"(a[2]), "r"(a[3]), "r"(b0), "r"(b1));
}

// ---------------- preprocessing: fused fp32 -> fp16 (A passthrough, W rint) --
constexpr int A_N4 = M_TOK * (K_IN / 4);           // 8388608 float4
constexpr int W_N4 = N_OUT * (K_IN / 4);           // 4194304 float4

__global__ void __launch_bounds__(256) cvt_fused_kernel(
    const float4* __restrict__ x, const float4* __restrict__ w)
{
    const int i = blockIdx.x * 256 + threadIdx.x;
    if (i < A_N4) {
        const float4 v = x[i];
        __half2 h01 = __floats2half2_rn(v.x, v.y);
        __half2 h23 = __floats2half2_rn(v.z, v.w);
        uint2 o;
        o.x = reinterpret_cast<unsigned&>(h01);
        o.y = reinterpret_cast<unsigned&>(h23);
        reinterpret_cast<uint2*>(g_Ah)[i] = o;
    } else {
        const int j = i - A_N4;
        const float4 v = w[j];
        __half2 h01 = __floats2half2_rn(rintf(v.x), rintf(v.y));
        __half2 h23 = __floats2half2_rn(rintf(v.z), rintf(v.w));
        uint2 o;
        o.x = reinterpret_cast<unsigned&>(h01);
        o.y = reinterpret_cast<unsigned&>(h23);
        reinterpret_cast<uint2*>(g_Wh)[j] = o;
    }
}

// ---------------- GEMM: mma.sync fp16, 4 warps x (64x64), 3-stage ring,
// cross-boundary fragment prefetch + CTA phase stagger ------------------------
// smem rows are 128B; swizzle: off = row*128 + (x ^ ((row&7)<<4)), x in [0,128)
__global__ void __launch_bounds__(128, 2) gemm_f16_kernel(
    const float* __restrict__ bias,
    const float* __restrict__ w_scale,
    const float* __restrict__ b_scale,
    float* __restrict__ out)
{
    extern __shared__ char smem[];
    const uint32_t sb = smem_u32(smem);
    const int tid = threadIdx.x;
    const int lid = tid & 31;
    const int wid = tid >> 5;        // 0..3
    const int wm  = wid >> 1;        // 0..1 -> warp M offset = wm*64
    const int wn  = wid & 1;         // 0..1 -> warp N offset = wn*64

    const int nt = blockIdx.x & (NT - 1);
    const int mt = blockIdx.x >> 5;
    const int m0 = mt * BM;
    const int n0 = nt * BN;
    // phase stagger: odd CTAs start K-loop 32 chunks in (circular) to
    // de-phase-lock the 2 co-resident CTAs' barriers on each SMSP.
    const int kphase = (blockIdx.x & 1) << 5;

    // ---- cp.async: 2048 x 16B per stage over 128 threads = 16 per thread
    const int cp_c = tid & 7;            // 16B chunk within 128B row
    const int cp_r = tid >> 3;           // 0..15
    const uint32_t cp_x = (uint32_t)(cp_c * 16);

    // ---- ldmatrix per-lane addressing (k-invariant parts hoisted)
    const int aRow = wm * 64 + (lid & 15);            // + im*16
    const int bRow = wn * 64 + (lid & 15);            // + ns*16
    const uint32_t khalf = (uint32_t)((lid >> 4) * 16);
    const uint32_t xorA  = (uint32_t)((aRow & 7) << 4);
    const uint32_t xorB  = (uint32_t)((bRow & 7) << 4);
    const uint32_t aOffBase = (uint32_t)(aRow * 128);
    const uint32_t bOffBase = (uint32_t)(A_BYTES + bRow * 128);
    uint32_t axk[4], bxk[4];
#pragma unroll
    for (int kk = 0; kk < 4; kk++) {
        axk[kk] = ((uint32_t)(kk * 32) + khalf) ^ xorA;
        bxk[kk] = ((uint32_t)(kk * 32) + khalf) ^ xorB;
    }

    float acc[4][8][4];
#pragma unroll
    for (int im = 0; im < 4; im++)
#pragma unroll
        for (int jn = 0; jn < 8; jn++)
#pragma unroll
            for (int r = 0; r < 4; r++) acc[im][jn][r] = 0.f;

    auto fill = [&](int s, int k) {
        const uint32_t sbase = sb + (uint32_t)(s * STAGE_B);
        const int kk0 = ((k + kphase) & (KCHUNKS - 1)) * BK;   // staggered source
#pragma unroll
        for (int t = 0; t < 8; t++) {                 // A: 128 rows
            const int row = t * 16 + cp_r;
            const uint32_t dst = sbase + (uint32_t)(row * 128) + (cp_x ^ ((uint32_t)(row & 7) << 4));
            cp16(dst, g_Ah + (size_t)(m0 + row) * K_IN + kk0 + cp_c * 8);
        }
#pragma unroll
        for (int t = 0; t < 8; t++) {                 // W: 128 rows
            const int row = t * 16 + cp_r;
            const uint32_t dst = sbase + (uint32_t)(A_BYTES + row * 128) + (cp_x ^ ((uint32_t)(row & 7) << 4));
            cp16(dst, g_Wh + (size_t)(n0 + row) * K_IN + kk0 + cp_c * 8);
        }
    };

    uint32_t a[2][4][4], b[2][4][4];   // double-buffered fragments
    auto ldfragA = [&](int buf, uint32_t aAddr, int kk) {
#pragma unroll
        for (int im = 0; im < 4; im++)
            ldsm4(a[buf][im][0], a[buf][im][1], a[buf][im][2], a[buf][im][3],
                  aAddr + (uint32_t)(im * 2048) + axk[kk]);
    };
    auto ldfragB = [&](int buf, uint32_t bAddr, int kk) {
#pragma unroll
        for (int ns = 0; ns < 4; ns++)
            ldsm4(b[buf][ns][0], b[buf][ns][1], b[buf][ns][2], b[buf][ns][3],
                  bAddr + (uint32_t)(ns * 2048) + bxk[kk]);
    };
    auto mmas = [&](int buf) {
#pragma unroll
        for (int im = 0; im < 4; im++)
#pragma unroll
            for (int ns = 0; ns < 4; ns++) {
                mma16816(acc[im][ns * 2],     a[buf][im], b[buf][ns][0], b[buf][ns][2]);
                mma16816(acc[im][ns * 2 + 1], a[buf][im], b[buf][ns][1], b[buf][ns][3]);
            }
    };

    // prologue: 2 stages in flight; stage 0 ready + kk0 fragments in regs
    fill(0, 0); cp_commit();
    fill(1, 1); cp_commit();
    cp_wait<1>();
    __syncthreads();
    {
        const uint32_t s0 = sb;
        ldfragB(0, s0 + bOffBase, 0);
        ldfragA(0, s0 + aOffBase, 0);
    }

    int cur = 0;
    for (int k = 0; k < KCHUNKS; k++) {
        const int s = k % STAGES;
        // invariant here: stage k visible to all warps; kk0 fragments of stage k
        // in buf[cur]; all warps past the barrier that ended chunk k-1, so stage
        // (k+2)%STAGES is safe to overwrite.
        const int kf = k + STAGES - 1;
        if (kf < KCHUNKS) fill(kf % STAGES, kf);
        cp_commit();                  // unconditional: fixed group accounting

        const uint32_t sbase = sb + (uint32_t)(s * STAGE_B);
        const uint32_t aAddr = sbase + aOffBase;
        const uint32_t bAddr = sbase + bOffBase;

#pragma unroll
        for (int kk = 0; kk < 3; kk++) {              // first 3 k16 steps
            const int nxt = cur ^ 1;
            ldfragB(nxt, bAddr, kk + 1);
            ldfragA(nxt, aAddr, kk + 1);
            mmas(cur);
            cur = nxt;
        }

        // boundary: wait for next stage + barrier BEFORE the last MMA block,
        // then prefetch next chunk's kk0 fragments under the last MMAs.
        cp_wait<1>();                 // fill(k+1) landed (fill(k+2) may pend)
        __syncthreads();              // stage k+1 visible; reads of stage s done
        if (k + 1 < KCHUNKS) {
            const uint32_t nbase = sb + (uint32_t)(((k + 1) % STAGES) * STAGE_B);
            const int nxt = cur ^ 1;
            ldfragB(nxt, nbase + bOffBase, 0);
            ldfragA(nxt, nbase + aOffBase, 0);
            mmas(cur);                // overlaps the prefetch above
            cur = nxt;
        } else {
            mmas(cur);
        }
    }

    // ---------------- epilogue: fuse w_scale, b_scale*rint(bias) ----------------
    const float wsc = __ldg(w_scale);
    const float bsc = __ldg(b_scale);
    const int rowb = m0 + wm * 64 + (lid >> 2);
    const int colb = n0 + wn * 64 + (lid & 3) * 2;

#pragma unroll
    for (int im = 0; im < 4; im++) {
        float* r0 = out + (size_t)(rowb + im * 16) * N_OUT;
        float* r1 = out + (size_t)(rowb + im * 16 + 8) * N_OUT;
#pragma unroll
        for (int jn = 0; jn < 8; jn++) {
            const float bb0 = bsc * rintf(__ldg(bias + colb + jn * 8));
            const float bb1 = bsc * rintf(__ldg(bias + colb + jn * 8 + 1));
            float2 v0, v1;
            v0.x = fmaf(wsc, acc[im][jn][0], bb0);
            v0.y = fmaf(wsc, acc[im][jn][1], bb1);
            v1.x = fmaf(wsc, acc[im][jn][2], bb0);
            v1.y = fmaf(wsc, acc[im][jn][3], bb1);
            *reinterpret_cast<float2*>(r0 + colb + jn * 8) = v0;
            *reinterpret_cast<float2*>(r1 + colb + jn * 8) = v1;
        }
    }
}

// ---------------- host launcher ----------------
extern "C" void kernel_launch(void* const* d_in, const int* in_sizes, int n_in,
                              void* d_out, int out_size)
{
    (void)in_sizes; (void)n_in; (void)out_size;
    const float* input   = (const float*)d_in[0];
    const float* weight  = (const float*)d_in[1];
    const float* bias    = (const float*)d_in[2];
    const float* w_scale = (const float*)d_in[3];
    const float* b_scale = (const float*)d_in[4];
    float* out = (float*)d_out;

    cudaFuncSetAttribute(gemm_f16_kernel,
                         cudaFuncAttributeMaxDynamicSharedMemorySize, SMEM_TOTAL);

    cvt_fused_kernel<<<(A_N4 + W_N4) / 256, 256>>>(
        (const float4*)input, (const float4*)weight);
    gemm_f16_kernel<<<MT * NT, 128, SMEM_TOTAL>>>(bias, w_scale, b_scale, out);
}

// round 17
// speedup vs baseline: 2.7456x; 2.7456x over previous
#include <cuda_runtime.h>
#include <cuda_fp16.h>
#include <cstdint>

#define DINLINE __device__ __forceinline__

// ---------------- problem constants ----------------
constexpr int M_TOK = 8192;
constexpr int N_OUT = 4096;
constexpr int K_IN  = 4096;

constexpr int BM = 128;
constexpr int BN = 128;
constexpr int BK = 64;                     // 64 fp16 = 128B row (swizzle atom)
constexpr int STAGES = 3;
constexpr int KCHUNKS = K_IN / BK;         // 64
constexpr int MT = M_TOK / BM;             // 64
constexpr int NT = N_OUT / BN;             // 32

constexpr int A_BYTES  = BM * BK * 2;      // 16384
constexpr int STAGE_B  = 2 * A_BYTES;      // 32768 (A + W)
constexpr int SMEM_TOTAL = STAGES * STAGE_B;  // 98304 -> 2 CTAs/SM

// ---------------- scratch (allocation-free: __device__ globals) ----------------
__device__ __align__(16) __half g_Ah[(size_t)M_TOK * K_IN];   // 64 MB
__device__ __align__(16) __half g_Wh[(size_t)N_OUT * K_IN];   // 32 MB

// ---------------- PTX helpers (sm_80-era, legal on plain compute_103) --------
DINLINE uint32_t smem_u32(const void* p) {
    uint32_t a;
    asm volatile("{ .reg .u64 t; cvta.to.shared.u64 t, %1; cvt.u32.u64 %0, t; }"
                 : "=r"(a) : "l"(p));
    return a;
}
DINLINE void cp16(uint32_t dst, const void* src) {
    asm volatile("cp.async.cg.shared.global [%0], [%1], 16;"
                 :: "r"(dst), "l"(__cvta_generic_to_global(src)) : "memory");
}
DINLINE void cp_commit() { asm volatile("cp.async.commit_group;" ::: "memory"); }
template <int N> DINLINE void cp_wait() {
    asm volatile("cp.async.wait_group %0;" :: "n"(N) : "memory");
}
DINLINE void ldsm4(uint32_t& r0, uint32_t& r1, uint32_t& r2, uint32_t& r3, uint32_t a) {
    asm volatile("ldmatrix.sync.aligned.m8n8.x4.shared.b16 {%0,%1,%2,%3}, [%4];"
                 : "=r"(r0), "=r"(r1), "=r"(r2), "=r"(r3) : "r"(a));
}
DINLINE void mma16816(float* c, const uint32_t* a, uint32_t b0, uint32_t b1) {
    asm volatile(
        "mma.sync.aligned.m16n8k16.row.col.f32.f16.f16.f32 "
        "{%0,%1,%2,%3}, {%4,%5,%6,%7}, {%8,%9}, {%0,%1,%2,%3};"
        : "+f"(c[0]), "+f"(c[1]), "+f"(c[2]), "+f"(c[3])
        : "r"(a[0]), "r"(a[1]), "r"(a[2]), "r"(a[3]), "r"(b0), "r"(b1));
}

// ---------------- preprocessing: fused fp32 -> fp16 (A passthrough, W rint) --
constexpr int A_N4 = M_TOK * (K_IN / 4);           // 8388608 float4
constexpr int W_N4 = N_OUT * (K_IN / 4);           // 4194304 float4

__global__ void __launch_bounds__(256) cvt_fused_kernel(
    const float4* __restrict__ x, const float4* __restrict__ w)
{
    const int i = blockIdx.x * 256 + threadIdx.x;
    if (i < A_N4) {
        const float4 v = x[i];
        __half2 h01 = __floats2half2_rn(v.x, v.y);
        __half2 h23 = __floats2half2_rn(v.z, v.w);
        uint2 o;
        o.x = reinterpret_cast<unsigned&>(h01);
        o.y = reinterpret_cast<unsigned&>(h23);
        reinterpret_cast<uint2*>(g_Ah)[i] = o;
    } else {
        const int j = i - A_N4;
        const float4 v = w[j];
        __half2 h01 = __floats2half2_rn(rintf(v.x), rintf(v.y));
        __half2 h23 = __floats2half2_rn(rintf(v.z), rintf(v.w));
        uint2 o;
        o.x = reinterpret_cast<unsigned&>(h01);
        o.y = reinterpret_cast<unsigned&>(h23);
        reinterpret_cast<uint2*>(g_Wh)[j] = o;
    }
}

// ---------------- GEMM: mma.sync fp16, 4 warps x (64x64), 3-stage ring ------
// R11 skeleton + minimal cross-boundary B prefetch (bpre, +16 regs only).
// smem rows are 128B; swizzle: off = row*128 + (x ^ ((row&7)<<4)), x in [0,128)
__global__ void __launch_bounds__(128, 2) gemm_f16_kernel(
    const float* __restrict__ bias,
    const float* __restrict__ w_scale,
    const float* __restrict__ b_scale,
    float* __restrict__ out)
{
    extern __shared__ char smem[];
    const uint32_t sb = smem_u32(smem);
    const int tid = threadIdx.x;
    const int lid = tid & 31;
    const int wid = tid >> 5;        // 0..3
    const int wm  = wid >> 1;        // 0..1 -> warp M offset = wm*64
    const int wn  = wid & 1;         // 0..1 -> warp N offset = wn*64

    const int nt = blockIdx.x & (NT - 1);
    const int mt = blockIdx.x >> 5;
    const int m0 = mt * BM;
    const int n0 = nt * BN;

    // ---- cp.async: 2048 x 16B per stage over 128 threads = 16 per thread
    const int cp_c = tid & 7;            // 16B chunk within 128B row
    const int cp_r = tid >> 3;           // 0..15
    const uint32_t cp_x = (uint32_t)(cp_c * 16);

    // ---- ldmatrix per-lane addressing (k-invariant parts hoisted)
    const int aRow = wm * 64 + (lid & 15);            // + im*16
    const int bRow = wn * 64 + (lid & 15);            // + ns*16
    const uint32_t khalf = (uint32_t)((lid >> 4) * 16);
    const uint32_t xorA  = (uint32_t)((aRow & 7) << 4);
    const uint32_t xorB  = (uint32_t)((bRow & 7) << 4);
    const uint32_t aOffBase = (uint32_t)(aRow * 128);
    const uint32_t bOffBase = (uint32_t)(A_BYTES + bRow * 128);
    uint32_t axk[4], bxk[4];
#pragma unroll
    for (int kk = 0; kk < 4; kk++) {
        axk[kk] = ((uint32_t)(kk * 32) + khalf) ^ xorA;
        bxk[kk] = ((uint32_t)(kk * 32) + khalf) ^ xorB;
    }

    float acc[4][8][4];
#pragma unroll
    for (int im = 0; im < 4; im++)
#pragma unroll
        for (int jn = 0; jn < 8; jn++)
#pragma unroll
            for (int r = 0; r < 4; r++) acc[im][jn][r] = 0.f;

    auto fill = [&](int s, int k) {
        const uint32_t sbase = sb + (uint32_t)(s * STAGE_B);
        const int kk0 = k * BK;
#pragma unroll
        for (int t = 0; t < 8; t++) {                 // A: 128 rows
            const int row = t * 16 + cp_r;
            const uint32_t dst = sbase + (uint32_t)(row * 128) + (cp_x ^ ((uint32_t)(row & 7) << 4));
            cp16(dst, g_Ah + (size_t)(m0 + row) * K_IN + kk0 + cp_c * 8);
        }
#pragma unroll
        for (int t = 0; t < 8; t++) {                 // W: 128 rows
            const int row = t * 16 + cp_r;
            const uint32_t dst = sbase + (uint32_t)(A_BYTES + row * 128) + (cp_x ^ ((uint32_t)(row & 7) << 4));
            cp16(dst, g_Wh + (size_t)(n0 + row) * K_IN + kk0 + cp_c * 8);
        }
    };

    // prologue: 2 stages in flight; then preload kk0 B fragments of stage 0
    fill(0, 0); cp_commit();
    fill(1, 1); cp_commit();
    cp_wait<1>();
    __syncthreads();

    uint32_t bpre[4][4];                 // kk0 B fragments of the CURRENT chunk
#pragma unroll
    for (int ns = 0; ns < 4; ns++)
        ldsm4(bpre[ns][0], bpre[ns][1], bpre[ns][2], bpre[ns][3],
              sb + bOffBase + (uint32_t)(ns * 2048) + bxk[0]);

    for (int k = 0; k < KCHUNKS; k++) {
        const int s = k % STAGES;
        // invariant: stage k visible; bpre holds its kk0 B fragments;
        // all warps past prior barrier -> stage (k+2)%3 safe to overwrite.
        const int kf = k + STAGES - 1;
        if (kf < KCHUNKS) fill(kf % STAGES, kf);
        cp_commit();                  // unconditional: fixed group accounting

        const uint32_t sbase = sb + (uint32_t)(s * STAGE_B);
        const uint32_t aAddr = sbase + aOffBase;
        const uint32_t bAddr = sbase + bOffBase;

        uint32_t a[4][4], b[4][4];

        // ---- kk = 0 : B comes from bpre (loaded under previous chunk's MMAs)
#pragma unroll
        for (int im = 0; im < 4; im++)
            ldsm4(a[im][0], a[im][1], a[im][2], a[im][3],
                  aAddr + (uint32_t)(im * 2048) + axk[0]);
#pragma unroll
        for (int im = 0; im < 4; im++)
#pragma unroll
            for (int ns = 0; ns < 4; ns++) {
                mma16816(acc[im][ns * 2],     a[im], bpre[ns][0], bpre[ns][2]);
                mma16816(acc[im][ns * 2 + 1], a[im], bpre[ns][1], bpre[ns][3]);
            }

        // ---- kk = 1, 2 : plain (ptxas software-pipelines within the chunk)
#pragma unroll
        for (int kk = 1; kk < 3; kk++) {
#pragma unroll
            for (int ns = 0; ns < 4; ns++)
                ldsm4(b[ns][0], b[ns][1], b[ns][2], b[ns][3],
                      bAddr + (uint32_t)(ns * 2048) + bxk[kk]);
#pragma unroll
            for (int im = 0; im < 4; im++)
                ldsm4(a[im][0], a[im][1], a[im][2], a[im][3],
                      aAddr + (uint32_t)(im * 2048) + axk[kk]);
#pragma unroll
            for (int im = 0; im < 4; im++)
#pragma unroll
                for (int ns = 0; ns < 4; ns++) {
                    mma16816(acc[im][ns * 2],     a[im], b[ns][0], b[ns][2]);
                    mma16816(acc[im][ns * 2 + 1], a[im], b[ns][1], b[ns][3]);
                }
        }

        // ---- kk = 3 : load fragments, THEN cross the boundary, THEN mma,
        //      with next chunk's kk0 B prefetch issued right after the barrier
        //      so the final 32 MMAs overlap it.
#pragma unroll
        for (int ns = 0; ns < 4; ns++)
            ldsm4(b[ns][0], b[ns][1], b[ns][2], b[ns][3],
                  bAddr + (uint32_t)(ns * 2048) + bxk[3]);
#pragma unroll
        for (int im = 0; im < 4; im++)
            ldsm4(a[im][0], a[im][1], a[im][2], a[im][3],
                  aAddr + (uint32_t)(im * 2048) + axk[3]);

        cp_wait<1>();                 // fill(k+1) landed (fill(k+2) may pend)
        __syncthreads();              // stage k+1 visible; reads of stage s done

        if (k + 1 < KCHUNKS) {
            const uint32_t nb = sb + (uint32_t)(((k + 1) % STAGES) * STAGE_B) + bOffBase;
#pragma unroll
            for (int ns = 0; ns < 4; ns++)
                ldsm4(bpre[ns][0], bpre[ns][1], bpre[ns][2], bpre[ns][3],
                      nb + (uint32_t)(ns * 2048) + bxk[0]);
        }
#pragma unroll
        for (int im = 0; im < 4; im++)
#pragma unroll
            for (int ns = 0; ns < 4; ns++) {
                mma16816(acc[im][ns * 2],     a[im], b[ns][0], b[ns][2]);
                mma16816(acc[im][ns * 2 + 1], a[im], b[ns][1], b[ns][3]);
            }
    }

    // ---------------- epilogue: fuse w_scale, b_scale*rint(bias) ----------------
    const float wsc = __ldg(w_scale);
    const float bsc = __ldg(b_scale);
    const int rowb = m0 + wm * 64 + (lid >> 2);
    const int colb = n0 + wn * 64 + (lid & 3) * 2;

#pragma unroll
    for (int im = 0; im < 4; im++) {
        float* r0 = out + (size_t)(rowb + im * 16) * N_OUT;
        float* r1 = out + (size_t)(rowb + im * 16 + 8) * N_OUT;
#pragma unroll
        for (int jn = 0; jn < 8; jn++) {
            const float bb0 = bsc * rintf(__ldg(bias + colb + jn * 8));
            const float bb1 = bsc * rintf(__ldg(bias + colb + jn * 8 + 1));
            float2 v0, v1;
            v0.x = fmaf(wsc, acc[im][jn][0], bb0);
            v0.y = fmaf(wsc, acc[im][jn][1], bb1);
            v1.x = fmaf(wsc, acc[im][jn][2], bb0);
            v1.y = fmaf(wsc, acc[im][jn][3], bb1);
            *reinterpret_cast<float2*>(r0 + colb + jn * 8) = v0;
            *reinterpret_cast<float2*>(r1 + colb + jn * 8) = v1;
        }
    }
}

// ---------------- host launcher ----------------
extern "C" void kernel_launch(void* const* d_in, const int* in_sizes, int n_in,
                              void* d_out, int out_size)
{
    (void)in_sizes; (void)n_in; (void)out_size;
    const float* input   = (const float*)d_in[0];
    const float* weight  = (const float*)d_in[1];
    const float* bias    = (const float*)d_in[2];
    const float* w_scale = (const float*)d_in[3];
    const float* b_scale = (const float*)d_in[4];
    float* out = (float*)d_out;

    cudaFuncSetAttribute(gemm_f16_kernel,
                         cudaFuncAttributeMaxDynamicSharedMemorySize, SMEM_TOTAL);

    cvt_fused_kernel<<<(A_N4 + W_N4) / 256, 256>>>(
        (const float4*)input, (const float4*)weight);
    gemm_f16_kernel<<<MT * NT, 128, SMEM_TOTAL>>>(bias, w_scale, b_scale, out);
}